// round 16
// baseline (speedup 1.0000x reference)
#include <cuda_runtime.h>
#include <cstdint>

// out[b,o,i,j] = sum_{c,ki,kj} x[b,c,i+ki,j+kj] * w[o,c,i,j,ki*3+kj] + bias[o,i,j]
// x[128,32,34,34] f32, w[64,32,32,32,9], bias[64,32,32], out[128,64,32,32].
//
// Kernel 0 (transpose_x): x[b][chw] -> xT[chw][b]  (makes GEMM A-loads coalesced)
// Kernel 1 (lc_gemm): one block per (i,j). GEMM M=128(b) x N=64(o) x K=288.
//   128 threads, 8m x 8n tiles, f32x2 FMAs packed along n. A rows are
//   b-contiguous in xT -> perfectly coalesced cp.async.16B. Writes
//   scratch[pos][b][o] coalesced.
// Kernel 2 (transpose_k): scratch[pos][bo] -> out[bo][pos].

#define CIN   32
#define COUT  64
#define HW    34
#define NPOS  1024
#define CHW   (CIN*HW*HW)      // 36992
#define NCH   8                // K chunks
#define CPC   4                // input channels per chunk
#define RPC   36               // k-rows per chunk (CPC*9)

#define AS_FLOATS (2*RPC*128)  // 9216 floats (36864 B)
#define WS_FLOATS (2*RPC*64)   // 4608 floats (18432 B)
#define SMEM_BYTES ((AS_FLOATS + WS_FLOATS)*4)   // 55296 B

__device__ float g_xT[CHW * 128];              // [c][h][w][b] 18.9 MB
__device__ float g_scratch[NPOS * 128 * 64];   // [pos][b][o]  33.5 MB

typedef unsigned long long ull;

__device__ __forceinline__ void cp16(uint32_t dst, const float* src) {
    asm volatile("cp.async.ca.shared.global [%0], [%1], 16;\n" :: "r"(dst), "l"(src));
}
__device__ __forceinline__ void cp4(uint32_t dst, const float* src) {
    asm volatile("cp.async.ca.shared.global [%0], [%1], 4;\n" :: "r"(dst), "l"(src));
}
__device__ __forceinline__ void cp_commit() {
    asm volatile("cp.async.commit_group;\n");
}
template <int N>
__device__ __forceinline__ void cp_wait() {
    asm volatile("cp.async.wait_group %0;\n" :: "n"(N));
}
__device__ __forceinline__ ull pack2(float v) {
    ull r;
    asm("mov.b64 %0, {%1, %1};" : "=l"(r) : "f"(v));
    return r;
}
__device__ __forceinline__ void ffma2(ull& acc, ull a, ull b) {
    asm("fma.rn.f32x2 %0, %1, %2, %0;" : "+l"(acc) : "l"(a), "l"(b));
}

// ---- Kernel 0: x[128][36992] -> xT[36992][128] ----
__global__ void __launch_bounds__(256)
transpose_x(const float* __restrict__ x)
{
    __shared__ float tile[32][33];
    const int s0 = blockIdx.x * 32;        // chw base (1156 tiles, exact)
    const int b0 = blockIdx.y * 32;        // b base   (4 tiles)
    const int tx = threadIdx.x & 31, ty = threadIdx.x >> 5;
    #pragma unroll
    for (int r = ty; r < 32; r += 8)
        tile[r][tx] = x[(b0 + r) * CHW + s0 + tx];
    __syncthreads();
    #pragma unroll
    for (int r = ty; r < 32; r += 8)
        g_xT[(s0 + r) * 128 + b0 + tx] = tile[tx][r];
}

// ---- Kernel 1: per-position GEMM ----
__global__ void __launch_bounds__(128, 4)
lc_gemm(const float* __restrict__ w,
        const float* __restrict__ bias)
{
    extern __shared__ float sm[];
    float* As = sm;              // [2][RPC][128]  k-rows, b contiguous
    float* Ws = sm + AS_FLOATS;  // [2][RPC][64]   k-rows, o contiguous

    const int pos = blockIdx.x;
    const int i = pos >> 5, j = pos & 31;
    const int tid = threadIdx.x;
    const int mt = tid >> 3, nt = tid & 7;   // 16 m-threads x 8 n-threads

    ull acc[8][4];
    #pragma unroll
    for (int u = 0; u < 8; ++u)
        #pragma unroll
        for (int q = 0; q < 4; ++q) acc[u][q] = 0ull;

    // A: 36 rows x 128 floats, fully coalesced 16B granules (1152 cp16 / 128 thr).
    auto loadA = [&](int t, int buf) {
        const int c0 = t * CPC;
        float* dstA = As + buf * RPC * 128;
        #pragma unroll
        for (int q = 0; q < 9; ++q) {
            int s    = tid + 128 * q;
            int row  = s >> 5;            // 0..35 = cc*9 + ki*3 + kj
            int slot = (s & 31) * 4;      // b nibble
            int cc = row / 9, k9 = row - cc * 9;
            int ki = k9 / 3, kj = k9 - ki * 3;
            const float* src = g_xT +
                (((c0 + cc) * HW + (i + ki)) * HW + (j + kj)) * 128 + slot;
            cp16((uint32_t)__cvta_generic_to_shared(dstA + row * 128 + slot), src);
        }
    };
    // W: 36B gmem segments -> 4B granules into [kk][o] (k-major, o contiguous).
    auto loadW = [&](int t, int buf) {
        const int c0 = t * CPC;
        float* dstW = Ws + buf * RPC * 64;
        #pragma unroll
        for (int q = 0; q < 18; ++q) {    // 36*64 / 128
            int s  = tid + 128 * q;
            int o  = s / RPC;
            int kk = s - o * RPC;
            int cc = kk / 9, k9 = kk - cc * 9;
            const float* src = w + ((o * CIN + c0 + cc) * NPOS + pos) * 9 + k9;
            cp4((uint32_t)__cvta_generic_to_shared(dstW + kk * 64 + o), src);
        }
    };

    loadA(0, 0); loadW(0, 0); cp_commit();

    for (int t = 0; t < NCH; ++t) {
        if (t + 1 < NCH) {
            loadA(t + 1, (t + 1) & 1);
            loadW(t + 1, (t + 1) & 1);
            cp_commit();
            cp_wait<1>();
        } else {
            cp_wait<0>();
        }
        __syncthreads();

        const float* A  = As + (t & 1) * RPC * 128 + 8 * mt;
        const float* Wt = Ws + (t & 1) * RPC * 64 + 8 * nt;

        #pragma unroll 4
        for (int k = 0; k < RPC; ++k) {
            float4 a0 = *(const float4*)(A + k * 128);       // b 0..3 (8-lane bcast)
            float4 a1 = *(const float4*)(A + k * 128 + 4);   // b 4..7
            ulonglong2 w0 = *(const ulonglong2*)(Wt + k * 64);      // o-pairs 0,1
            ulonglong2 w1 = *(const ulonglong2*)(Wt + k * 64 + 4);  // o-pairs 2,3
            ull ad[8];
            ad[0] = pack2(a0.x); ad[1] = pack2(a0.y);
            ad[2] = pack2(a0.z); ad[3] = pack2(a0.w);
            ad[4] = pack2(a1.x); ad[5] = pack2(a1.y);
            ad[6] = pack2(a1.z); ad[7] = pack2(a1.w);
            #pragma unroll
            for (int u = 0; u < 8; ++u) {
                ffma2(acc[u][0], ad[u], w0.x);
                ffma2(acc[u][1], ad[u], w0.y);
                ffma2(acc[u][2], ad[u], w1.x);
                ffma2(acc[u][3], ad[u], w1.y);
            }
        }
        __syncthreads();
    }

    // Epilogue: bias + coalesced float4 stores into scratch[pos][b][o].
    float bv[8];
    #pragma unroll
    for (int q = 0; q < 8; ++q)
        bv[q] = bias[(8 * nt + q) * NPOS + pos];

    float* sc = g_scratch + pos * (128 * 64) + 8 * nt;
    #pragma unroll
    for (int u = 0; u < 8; ++u) {
        const int b = 8 * mt + u;
        #pragma unroll
        for (int g = 0; g < 2; ++g) {
            float2 p0 = *(float2*)&acc[u][2 * g];
            float2 p1 = *(float2*)&acc[u][2 * g + 1];
            float4 v;
            v.x = p0.x + bv[4 * g + 0];
            v.y = p0.y + bv[4 * g + 1];
            v.z = p1.x + bv[4 * g + 2];
            v.w = p1.y + bv[4 * g + 3];
            *(float4*)(sc + b * 64 + 4 * g) = v;
        }
    }
}

// ---- Kernel 2: scratch[pos][bo] -> out[bo][pos] ----
__global__ void __launch_bounds__(256)
transpose_k(float* __restrict__ out)
{
    __shared__ float tile[32][33];
    const int bo0 = blockIdx.x * 32;
    const int p0  = blockIdx.y * 32;
    const int tx = threadIdx.x & 31, ty = threadIdx.x >> 5;
    #pragma unroll
    for (int r = ty; r < 32; r += 8)
        tile[r][tx] = g_scratch[(p0 + r) * (128 * 64) + bo0 + tx];
    __syncthreads();
    #pragma unroll
    for (int r = ty; r < 32; r += 8)
        out[(bo0 + r) * NPOS + p0 + tx] = tile[tx][r];
}

extern "C" void kernel_launch(void* const* d_in, const int* in_sizes, int n_in,
                              void* d_out, int out_size)
{
    (void)in_sizes; (void)n_in; (void)out_size;
    const float* x    = (const float*)d_in[0];
    const float* w    = (const float*)d_in[1];
    const float* bias = (const float*)d_in[2];
    float* out        = (float*)d_out;

    cudaFuncSetAttribute(lc_gemm,
                         cudaFuncAttributeMaxDynamicSharedMemorySize, SMEM_BYTES);
    transpose_x<<<dim3(CHW / 32, 4), 256>>>(x);
    lc_gemm<<<NPOS, 128, SMEM_BYTES>>>(w, bias);
    transpose_k<<<dim3(128 * 64 / 32, NPOS / 32), 256>>>(out);
}

// round 17
// speedup vs baseline: 1.0028x; 1.0028x over previous
#include <cuda_runtime.h>
#include <cstdint>

// out[b,o,i,j] = sum_{c,ki,kj} x[b,c,i+ki,j+kj] * w[o,c,i,j,ki*3+kj] + bias[o,i,j]
// x[128,32,34,34] f32, w[64,32,32,32,9], bias[64,32,32], out[128,64,32,32].
//
// Kernel 0 (transpose_x): x[b][chw] -> xT[chw][b]  (makes GEMM A-loads coalesced)
// Kernel 1 (lc_gemm): one block per (i,j). GEMM M=128(b) x N=64(o) x K=288.
//   128 threads, 8m x 8n tiles, f32x2 FMAs packed along n. A rows are
//   b-contiguous in xT -> perfectly coalesced cp.async.16B. Writes
//   scratch[pos][b][o] coalesced.
// Kernel 2 (transpose_k): scratch[pos][bo] -> out[bo][pos].

#define CIN   32
#define COUT  64
#define HW    34
#define NPOS  1024
#define CHW   (CIN*HW*HW)      // 36992
#define NCH   8                // K chunks
#define CPC   4                // input channels per chunk
#define RPC   36               // k-rows per chunk (CPC*9)

#define AS_FLOATS (2*RPC*128)  // 9216 floats (36864 B)
#define WS_FLOATS (2*RPC*64)   // 4608 floats (18432 B)
#define SMEM_BYTES ((AS_FLOATS + WS_FLOATS)*4)   // 55296 B

__device__ float g_xT[CHW * 128];              // [c][h][w][b] 18.9 MB
__device__ float g_scratch[NPOS * 128 * 64];   // [pos][b][o]  33.5 MB

typedef unsigned long long ull;

__device__ __forceinline__ void cp16(uint32_t dst, const float* src) {
    asm volatile("cp.async.ca.shared.global [%0], [%1], 16;\n" :: "r"(dst), "l"(src));
}
__device__ __forceinline__ void cp4(uint32_t dst, const float* src) {
    asm volatile("cp.async.ca.shared.global [%0], [%1], 4;\n" :: "r"(dst), "l"(src));
}
__device__ __forceinline__ void cp_commit() {
    asm volatile("cp.async.commit_group;\n");
}
template <int N>
__device__ __forceinline__ void cp_wait() {
    asm volatile("cp.async.wait_group %0;\n" :: "n"(N));
}
__device__ __forceinline__ ull pack2(float v) {
    ull r;
    asm("mov.b64 %0, {%1, %1};" : "=l"(r) : "f"(v));
    return r;
}
__device__ __forceinline__ void ffma2(ull& acc, ull a, ull b) {
    asm("fma.rn.f32x2 %0, %1, %2, %0;" : "+l"(acc) : "l"(a), "l"(b));
}

// ---- Kernel 0: x[128][36992] -> xT[36992][128] ----
__global__ void __launch_bounds__(256)
transpose_x(const float* __restrict__ x)
{
    __shared__ float tile[32][33];
    const int s0 = blockIdx.x * 32;        // chw base (1156 tiles, exact)
    const int b0 = blockIdx.y * 32;        // b base   (4 tiles)
    const int tx = threadIdx.x & 31, ty = threadIdx.x >> 5;
    #pragma unroll
    for (int r = ty; r < 32; r += 8)
        tile[r][tx] = x[(b0 + r) * CHW + s0 + tx];
    __syncthreads();
    #pragma unroll
    for (int r = ty; r < 32; r += 8)
        g_xT[(s0 + r) * 128 + b0 + tx] = tile[tx][r];
}

// ---- Kernel 1: per-position GEMM ----
__global__ void __launch_bounds__(128, 4)
lc_gemm(const float* __restrict__ w,
        const float* __restrict__ bias)
{
    extern __shared__ float sm[];
    float* As = sm;              // [2][RPC][128]  k-rows, b contiguous
    float* Ws = sm + AS_FLOATS;  // [2][RPC][64]   k-rows, o contiguous

    const int pos = blockIdx.x;
    const int i = pos >> 5, j = pos & 31;
    const int tid = threadIdx.x;
    const int mt = tid >> 3, nt = tid & 7;   // 16 m-threads x 8 n-threads

    ull acc[8][4];
    #pragma unroll
    for (int u = 0; u < 8; ++u)
        #pragma unroll
        for (int q = 0; q < 4; ++q) acc[u][q] = 0ull;

    // A: 36 rows x 128 floats, fully coalesced 16B granules (1152 cp16 / 128 thr).
    auto loadA = [&](int t, int buf) {
        const int c0 = t * CPC;
        float* dstA = As + buf * RPC * 128;
        #pragma unroll
        for (int q = 0; q < 9; ++q) {
            int s    = tid + 128 * q;
            int row  = s >> 5;            // 0..35 = cc*9 + ki*3 + kj
            int slot = (s & 31) * 4;      // b nibble
            int cc = row / 9, k9 = row - cc * 9;
            int ki = k9 / 3, kj = k9 - ki * 3;
            const float* src = g_xT +
                (((c0 + cc) * HW + (i + ki)) * HW + (j + kj)) * 128 + slot;
            cp16((uint32_t)__cvta_generic_to_shared(dstA + row * 128 + slot), src);
        }
    };
    // W: 36B gmem segments -> 4B granules into [kk][o] (k-major, o contiguous).
    auto loadW = [&](int t, int buf) {
        const int c0 = t * CPC;
        float* dstW = Ws + buf * RPC * 64;
        #pragma unroll
        for (int q = 0; q < 18; ++q) {    // 36*64 / 128
            int s  = tid + 128 * q;
            int o  = s / RPC;
            int kk = s - o * RPC;
            int cc = kk / 9, k9 = kk - cc * 9;
            const float* src = w + ((o * CIN + c0 + cc) * NPOS + pos) * 9 + k9;
            cp4((uint32_t)__cvta_generic_to_shared(dstW + kk * 64 + o), src);
        }
    };

    loadA(0, 0); loadW(0, 0); cp_commit();

    for (int t = 0; t < NCH; ++t) {
        if (t + 1 < NCH) {
            loadA(t + 1, (t + 1) & 1);
            loadW(t + 1, (t + 1) & 1);
            cp_commit();
            cp_wait<1>();
        } else {
            cp_wait<0>();
        }
        __syncthreads();

        const float* A  = As + (t & 1) * RPC * 128 + 8 * mt;
        const float* Wt = Ws + (t & 1) * RPC * 64 + 8 * nt;

        #pragma unroll 4
        for (int k = 0; k < RPC; ++k) {
            float4 a0 = *(const float4*)(A + k * 128);       // b 0..3 (8-lane bcast)
            float4 a1 = *(const float4*)(A + k * 128 + 4);   // b 4..7
            ulonglong2 w0 = *(const ulonglong2*)(Wt + k * 64);      // o-pairs 0,1
            ulonglong2 w1 = *(const ulonglong2*)(Wt + k * 64 + 4);  // o-pairs 2,3
            ull ad[8];
            ad[0] = pack2(a0.x); ad[1] = pack2(a0.y);
            ad[2] = pack2(a0.z); ad[3] = pack2(a0.w);
            ad[4] = pack2(a1.x); ad[5] = pack2(a1.y);
            ad[6] = pack2(a1.z); ad[7] = pack2(a1.w);
            #pragma unroll
            for (int u = 0; u < 8; ++u) {
                ffma2(acc[u][0], ad[u], w0.x);
                ffma2(acc[u][1], ad[u], w0.y);
                ffma2(acc[u][2], ad[u], w1.x);
                ffma2(acc[u][3], ad[u], w1.y);
            }
        }
        __syncthreads();
    }

    // Epilogue: bias + coalesced float4 stores into scratch[pos][b][o].
    float bv[8];
    #pragma unroll
    for (int q = 0; q < 8; ++q)
        bv[q] = bias[(8 * nt + q) * NPOS + pos];

    float* sc = g_scratch + pos * (128 * 64) + 8 * nt;
    #pragma unroll
    for (int u = 0; u < 8; ++u) {
        const int b = 8 * mt + u;
        #pragma unroll
        for (int g = 0; g < 2; ++g) {
            float2 p0 = *(float2*)&acc[u][2 * g];
            float2 p1 = *(float2*)&acc[u][2 * g + 1];
            float4 v;
            v.x = p0.x + bv[4 * g + 0];
            v.y = p0.y + bv[4 * g + 1];
            v.z = p1.x + bv[4 * g + 2];
            v.w = p1.y + bv[4 * g + 3];
            *(float4*)(sc + b * 64 + 4 * g) = v;
        }
    }
}

// ---- Kernel 2: scratch[pos][bo] -> out[bo][pos] ----
__global__ void __launch_bounds__(256)
transpose_k(float* __restrict__ out)
{
    __shared__ float tile[32][33];
    const int bo0 = blockIdx.x * 32;
    const int p0  = blockIdx.y * 32;
    const int tx = threadIdx.x & 31, ty = threadIdx.x >> 5;
    #pragma unroll
    for (int r = ty; r < 32; r += 8)
        tile[r][tx] = g_scratch[(p0 + r) * (128 * 64) + bo0 + tx];
    __syncthreads();
    #pragma unroll
    for (int r = ty; r < 32; r += 8)
        out[(bo0 + r) * NPOS + p0 + tx] = tile[tx][r];
}

extern "C" void kernel_launch(void* const* d_in, const int* in_sizes, int n_in,
                              void* d_out, int out_size)
{
    (void)in_sizes; (void)n_in; (void)out_size;
    const float* x    = (const float*)d_in[0];
    const float* w    = (const float*)d_in[1];
    const float* bias = (const float*)d_in[2];
    float* out        = (float*)d_out;

    cudaFuncSetAttribute(lc_gemm,
                         cudaFuncAttributeMaxDynamicSharedMemorySize, SMEM_BYTES);
    transpose_x<<<dim3(CHW / 32, 4), 256>>>(x);
    lc_gemm<<<NPOS, 128, SMEM_BYTES>>>(w, bias);
    transpose_k<<<dim3(128 * 64 / 32, NPOS / 32), 256>>>(out);
}